// round 3
// baseline (speedup 1.0000x reference)
#include <cuda_runtime.h>
#include <math.h>

// Problem constants
#define Bn 2
#define Nn 1024
#define Dn 1024
#define Hn 16
#define HDn 64
#define BHn 32
#define NBn 16   // number of 64-row blocks along sequence

typedef float2 f2;
#define TP 66                          // padded width (in float2) of split tiles
#define TILE_B (sizeof(f2)*64*TP)      // 33792 bytes per split tile

// ---------------- device scratch ----------------
__device__ float g_qf[Bn*Nn*Dn];
__device__ float g_kf[Bn*Nn*Dn];
__device__ float g_vf[Bn*Nn*Dn];
__device__ float g_wf[Bn*Nn*Dn];
__device__ float g_w1[Bn*Nn*HDn];
__device__ float g_bb[Bn*Nn*Hn];
__device__ float g_ff[Bn*Nn*Hn];

__device__ float g_q[BHn*Nn*HDn];   // [bh][n][hd]
__device__ float g_k[BHn*Nn*HDn];
__device__ float g_v[BHn*Nn*HDn];
__device__ float g_w[BHn*Nn*HDn];
__device__ float g_beta[BHn*Nn];
__device__ float g_lf[BHn*Nn];
__device__ float g_Fc[BHn*Nn];
__device__ float g_Tinv[BHn*NBn*64*64];
__device__ float g_LG[(size_t)BHn*Nn*Nn];   // L blocks during solve; dense G afterwards
__device__ float g_C[(size_t)BHn*Nn*Nn];
__device__ float g_S[(size_t)BHn*Nn*Nn];
__device__ float g_o[Bn*Nn*Dn];

// ---------------- tf32 3x-split helpers ----------------
__device__ __forceinline__ f2 splt(float x) {
    unsigned h, l;
    asm("cvt.rna.tf32.f32 %0, %1;" : "=r"(h) : "f"(x));
    float hf = __uint_as_float(h);
    float lof = x - hf;
    asm("cvt.rna.tf32.f32 %0, %1;" : "=r"(l) : "f"(lof));
    return make_float2(hf, __uint_as_float(l));
}

__device__ __forceinline__ void mma_raw(float c[4], float a0, float a1, float a2, float a3,
                                        float b0, float b1) {
    unsigned A0 = __float_as_uint(a0), A1 = __float_as_uint(a1);
    unsigned A2 = __float_as_uint(a2), A3 = __float_as_uint(a3);
    unsigned B0 = __float_as_uint(b0), B1 = __float_as_uint(b1);
    asm volatile(
        "mma.sync.aligned.m16n8k8.row.col.f32.tf32.tf32.f32 "
        "{%0,%1,%2,%3}, {%4,%5,%6,%7}, {%8,%9}, {%0,%1,%2,%3};"
        : "+f"(c[0]), "+f"(c[1]), "+f"(c[2]), "+f"(c[3])
        : "r"(A0), "r"(A1), "r"(A2), "r"(A3), "r"(B0), "r"(B1));
}

// Warp computes a 16x32 region of a 64x64x64 tile product.
// A is logical [m][k]. BT=true: B stored [n][k] (dot of rows, NT). BT=false: B stored [k][n] (NN).
template<bool BT>
__device__ __forceinline__ void wtile(float acc[4][4], const f2 (*A)[TP], const f2 (*B)[TP],
                                      int m0, int n0) {
    int lane = threadIdx.x & 31;
    int g = lane >> 2, tig = lane & 3;
#pragma unroll
    for (int k0 = 0; k0 < 64; k0 += 8) {
        f2 A0 = A[m0 + g][k0 + tig];
        f2 A1 = A[m0 + g + 8][k0 + tig];
        f2 A2 = A[m0 + g][k0 + tig + 4];
        f2 A3 = A[m0 + g + 8][k0 + tig + 4];
#pragma unroll
        for (int nf = 0; nf < 4; nf++) {
            int nn = n0 + nf * 8 + g;
            f2 B0 = BT ? B[nn][k0 + tig]     : B[k0 + tig][nn];
            f2 B1 = BT ? B[nn][k0 + tig + 4] : B[k0 + tig + 4][nn];
            mma_raw(acc[nf], A0.x, A1.x, A2.x, A3.x, B0.x, B1.x);  // hi*hi
            mma_raw(acc[nf], A0.x, A1.x, A2.x, A3.x, B0.y, B1.y);  // hi*lo
            mma_raw(acc[nf], A0.y, A1.y, A2.y, A3.y, B0.x, B1.x);  // lo*hi
        }
    }
}

// Load a 64x64 fp32 tile into split (hi,lo) smem. sgn=-1 to negate (for subtraction).
__device__ __forceinline__ void ldtile(f2 (*sm)[TP], const float* __restrict__ g, int stride, float sgn) {
    int t = threadIdx.x;
    int r = t >> 2;
    int c0 = (t & 3) << 4;
    const float* gp = g + (size_t)r * stride + c0;
#pragma unroll
    for (int q = 0; q < 4; q++) {
        float4 v = *(const float4*)(gp + 4 * q);
        sm[r][c0 + 4*q + 0] = splt(sgn * v.x);
        sm[r][c0 + 4*q + 1] = splt(sgn * v.y);
        sm[r][c0 + 4*q + 2] = splt(sgn * v.z);
        sm[r][c0 + 4*q + 3] = splt(sgn * v.w);
    }
}

// Per-thread epilogue coordinates for the 8-warp tiling of a 64x64 tile.
#define EPI_COORDS \
    int lane = threadIdx.x & 31, wrp = threadIdx.x >> 5; \
    int g = lane >> 2, tig = lane & 3; \
    int wm = (wrp & 3) * 16, wn = (wrp >> 2) * 32; \
    (void)g; (void)tig; (void)wm; (void)wn;

// ---------------- tensor-core tiled GEMM: C[MxN] = A[MxK] @ B[KxN], all dims %64==0 ----------------
__global__ void gemm_tc(const float* __restrict__ A, const float* __restrict__ B,
                        float* __restrict__ C, int M, int N, int K) {
    extern __shared__ char sraw[];
    f2 (*sA)[TP] = (f2(*)[TP])sraw;
    f2 (*sB)[TP] = (f2(*)[TP])(sraw + TILE_B);
    int m0b = blockIdx.y * 64, n0b = blockIdx.x * 64;
    EPI_COORDS;
    float acc[4][4] = {};
    for (int k0 = 0; k0 < K; k0 += 64) {
        __syncthreads();
        ldtile(sA, A + (size_t)m0b * K + k0, K, 1.f);
        ldtile(sB, B + (size_t)k0 * N + n0b, N, 1.f);
        __syncthreads();
        wtile<false>(acc, sA, sB, wm, wn);
    }
#pragma unroll
    for (int nf = 0; nf < 4; nf++) {
        int col = n0b + wn + nf * 8 + 2 * tig;
        int r0 = m0b + wm + g, r1 = r0 + 8;
        C[(size_t)r0 * N + col]     = acc[nf][0];
        C[(size_t)r0 * N + col + 1] = acc[nf][1];
        C[(size_t)r1 * N + col]     = acc[nf][2];
        C[(size_t)r1 * N + col + 1] = acc[nf][3];
    }
}

// ---------------- scalar GEMM for tiny N (Wb/Wf, N=16) ----------------
__global__ void gemm_kernel(const float* __restrict__ A, const float* __restrict__ Bm,
                            float* __restrict__ C, int M, int Ncols, int K) {
    __shared__ float As[16][65];
    __shared__ float Bs[16][65];
    int m0 = blockIdx.y * 64, n0 = blockIdx.x * 64;
    int tid = threadIdx.x;
    int ty = (tid >> 4) << 2, tx = (tid & 15) << 2;
    int lrA = tid >> 2, lcA = (tid & 3) << 2;
    int krB = tid >> 4, ncB = (tid & 15) << 2;
    float acc[4][4] = {};
    for (int k0 = 0; k0 < K; k0 += 16) {
        float4 va = *(const float4*)(A + (size_t)(m0 + lrA) * K + k0 + lcA);
        As[lcA + 0][lrA] = va.x;
        As[lcA + 1][lrA] = va.y;
        As[lcA + 2][lrA] = va.z;
        As[lcA + 3][lrA] = va.w;
#pragma unroll
        for (int q = 0; q < 4; q++) {
            int col = n0 + ncB + q;
            Bs[krB][ncB + q] = (col < Ncols) ? Bm[(size_t)(k0 + krB) * Ncols + col] : 0.f;
        }
        __syncthreads();
#pragma unroll
        for (int kk = 0; kk < 16; kk++) {
            float a[4], b[4];
#pragma unroll
            for (int i = 0; i < 4; i++) a[i] = As[kk][ty + i];
#pragma unroll
            for (int j = 0; j < 4; j++) b[j] = Bs[kk][tx + j];
#pragma unroll
            for (int i = 0; i < 4; i++)
#pragma unroll
                for (int j = 0; j < 4; j++)
                    acc[i][j] += a[i] * b[j];
        }
        __syncthreads();
    }
#pragma unroll
    for (int i = 0; i < 4; i++)
#pragma unroll
        for (int j = 0; j < 4; j++) {
            int col = n0 + tx + j;
            if (col < Ncols) C[(size_t)(m0 + ty + i) * Ncols + col] = acc[i][j];
        }
}

// ---------------- reorg: head layout, w-normalize, beta, log-sigmoid gate ----------------
__global__ void reorg_kernel(const float* __restrict__ delta) {
    int bn = blockIdx.x;
    int b = bn >> 10, n = bn & 1023;
    int tid = threadIdx.x;
    __shared__ float wrow[Dn];
    __shared__ float rn[Hn];
    for (int e = tid; e < Dn; e += 256) {
        int h = e >> 6, c = e & 63;
        int src = bn * Dn + e;
        int dst = ((b * Hn + h) * Nn + n) * HDn + c;
        g_q[dst] = g_qf[src];
        g_k[dst] = g_kf[src];
        g_v[dst] = g_vf[src];
        wrow[e] = g_wf[src];
    }
    __syncthreads();
    if (tid < Hn) {
        float s = 1e-6f;
        for (int c = 0; c < HDn; c++) { float w = wrow[tid * HDn + c]; s += w * w; }
        rn[tid] = rsqrtf(s);
        float bbv = g_bb[bn * Hn + tid];
        g_beta[(b * Hn + tid) * Nn + n] = 2.f / (1.f + expf(-bbv));
        float z = g_ff[bn * Hn + tid] + delta[tid];
        g_lf[(b * Hn + tid) * Nn + n] = fminf(z, 0.f) - log1pf(expf(-fabsf(z)));
    }
    __syncthreads();
    for (int e = tid; e < Dn; e += 256) {
        int h = e >> 6, c = e & 63;
        g_w[((b * Hn + h) * Nn + n) * HDn + c] = wrow[e] * rn[h];
    }
}

// ---------------- cumulative sum of log gates per (b,h) ----------------
__global__ void cumsum_kernel() {
    int bh = blockIdx.x, tid = threadIdx.x;
    __shared__ float part[256];
    const float* lf = g_lf + bh * Nn;
    float v0 = lf[tid * 4 + 0];
    float v1 = lf[tid * 4 + 1];
    float v2 = lf[tid * 4 + 2];
    float v3 = lf[tid * 4 + 3];
    v1 += v0; v2 += v1; v3 += v2;
    part[tid] = v3;
    __syncthreads();
    if (tid == 0) {
        float run = 0.f;
        for (int t = 0; t < 256; t++) { float tmp = part[t]; part[t] = run; run += tmp; }
    }
    __syncthreads();
    float off = part[tid];
    g_Fc[bh * Nn + tid * 4 + 0] = off + v0;
    g_Fc[bh * Nn + tid * 4 + 1] = off + v1;
    g_Fc[bh * Nn + tid * 4 + 2] = off + v2;
    g_Fc[bh * Nn + tid * 4 + 3] = off + v3;
}

// ---------------- L blocks: L[i][r] = (w_i @ w_r^T) * beta_r (r<i) ----------------
__global__ void l_kernel() {
    int bx = blockIdx.x;
    int i = bx >> 4, r = bx & 15;
    if (r >= i) return;
    int bh = blockIdx.y;
    extern __shared__ char sraw[];
    f2 (*sA)[TP] = (f2(*)[TP])sraw;
    f2 (*sB)[TP] = (f2(*)[TP])(sraw + TILE_B);
    ldtile(sA, g_w + ((size_t)bh * Nn + i * 64) * HDn, HDn, 1.f);
    ldtile(sB, g_w + ((size_t)bh * Nn + r * 64) * HDn, HDn, 1.f);
    __syncthreads();
    EPI_COORDS;
    float acc[4][4] = {};
    wtile<true>(acc, sA, sB, wm, wn);
    float* out = g_LG + (((size_t)bh * NBn + i) * NBn + r) * 4096;
    const float* bet = g_beta + bh * Nn + r * 64;
#pragma unroll
    for (int nf = 0; nf < 4; nf++) {
        int c = wn + nf * 8 + 2 * tig;
        int r0 = wm + g, r1 = r0 + 8;
        out[r0 * 64 + c]     = acc[nf][0] * bet[c];
        out[r0 * 64 + c + 1] = acc[nf][1] * bet[c + 1];
        out[r1 * 64 + c]     = acc[nf][2] * bet[c];
        out[r1 * 64 + c + 1] = acc[nf][3] * bet[c + 1];
    }
}

// ---------------- Tinv: (I + L_ii)^-1 ----------------
__global__ void tinv_kernel() {
    int i = blockIdx.x, bh = blockIdx.y, tid = threadIdx.x;
    extern __shared__ char sraw[];
    f2 (*sW)[TP] = (f2(*)[TP])sraw;
    float (*Ml)[65] = (float(*)[65])(sraw + TILE_B);
    float (*X)[65]  = (float(*)[65])(sraw + TILE_B + 64 * 65 * sizeof(float));
    ldtile(sW, g_w + ((size_t)bh * Nn + i * 64) * HDn, HDn, 1.f);
    __syncthreads();
    EPI_COORDS;
    float acc[4][4] = {};
    wtile<true>(acc, sW, sW, wm, wn);
    const float* bet = g_beta + bh * Nn + i * 64;
#pragma unroll
    for (int nf = 0; nf < 4; nf++) {
        int c = wn + nf * 8 + 2 * tig;
        int s0 = wm + g, s1 = s0 + 8;
        Ml[s0][c]     = (c     < s0) ? acc[nf][0] * bet[c]     : 0.f;
        Ml[s0][c + 1] = (c + 1 < s0) ? acc[nf][1] * bet[c + 1] : 0.f;
        Ml[s1][c]     = (c     < s1) ? acc[nf][2] * bet[c]     : 0.f;
        Ml[s1][c + 1] = (c + 1 < s1) ? acc[nf][3] * bet[c + 1] : 0.f;
    }
    __syncthreads();
    if (tid < 64) {
        int c = tid;
        X[c][c] = 1.f;
        for (int rr = c + 1; rr < 64; rr++) {
            float s = 0.f;
            for (int m = c; m < rr; m++) s += Ml[rr][m] * X[m][c];
            X[rr][c] = -s;
        }
    }
    __syncthreads();
    float* out = g_Tinv + ((size_t)bh * NBn + i) * 4096;
    for (int e = tid; e < 4096; e += 256) {
        int rr = e >> 6, cc = e & 63;
        out[e] = (rr > cc) ? X[rr][cc] : (rr == cc ? 1.f : 0.f);
    }
}

// ---------------- solve step (block row i): C_ij = Tinv_i (M_ij - sum_r L_ir C_rj) ----------------
__global__ void solve_kernel(int i) {
    int j = blockIdx.x;
    int bh = blockIdx.y;
    extern __shared__ char sraw[];
    f2 (*sA)[TP] = (f2(*)[TP])sraw;
    f2 (*sB)[TP] = (f2(*)[TP])(sraw + TILE_B);
    EPI_COORDS;
    float acc[4][4] = {};
    ldtile(sA, g_w + ((size_t)bh * Nn + i * 64) * HDn, HDn, 1.f);
    ldtile(sB, g_k + ((size_t)bh * Nn + j * 64) * HDn, HDn, 1.f);
    __syncthreads();
    wtile<true>(acc, sA, sB, wm, wn);
    if (i == j) {
#pragma unroll
        for (int nf = 0; nf < 4; nf++) {
            int c = wn + nf * 8 + 2 * tig;
            int r0 = wm + g, r1 = r0 + 8;
            if (r0 <= c)     acc[nf][0] = 0.f;
            if (r0 <= c + 1) acc[nf][1] = 0.f;
            if (r1 <= c)     acc[nf][2] = 0.f;
            if (r1 <= c + 1) acc[nf][3] = 0.f;
        }
    }
    for (int r = j; r < i; r++) {
        __syncthreads();
        ldtile(sA, g_LG + (((size_t)bh * NBn + i) * NBn + r) * 4096, 64, -1.f);
        ldtile(sB, g_C + ((size_t)bh * Nn + r * 64) * Nn + j * 64, Nn, 1.f);
        __syncthreads();
        wtile<false>(acc, sA, sB, wm, wn);
    }
    __syncthreads();
    // scatter R into sB (split), load Tinv into sA
#pragma unroll
    for (int nf = 0; nf < 4; nf++) {
        int c = wn + nf * 8 + 2 * tig;
        int r0 = wm + g, r1 = r0 + 8;
        sB[r0][c]     = splt(acc[nf][0]);
        sB[r0][c + 1] = splt(acc[nf][1]);
        sB[r1][c]     = splt(acc[nf][2]);
        sB[r1][c + 1] = splt(acc[nf][3]);
    }
    ldtile(sA, g_Tinv + ((size_t)bh * NBn + i) * 4096, 64, 1.f);
    __syncthreads();
    float acc2[4][4] = {};
    wtile<false>(acc2, sA, sB, wm, wn);
    float* out = g_C + ((size_t)bh * Nn + i * 64) * Nn + j * 64;
#pragma unroll
    for (int nf = 0; nf < 4; nf++) {
        int c = wn + nf * 8 + 2 * tig;
        int r0 = wm + g, r1 = r0 + 8;
        out[r0 * Nn + c]     = acc2[nf][0];
        out[r0 * Nn + c + 1] = acc2[nf][1];
        out[r1 * Nn + c]     = acc2[nf][2];
        out[r1 * Nn + c + 1] = acc2[nf][3];
    }
}

// ---------------- G = tril(q w^T) * beta_s (dense, into g_LG) ----------------
__global__ void g_kernel() {
    int bx = blockIdx.x;
    int ti = bx >> 4, tj = bx & 15;
    if (tj > ti) return;
    int bh = blockIdx.y;
    extern __shared__ char sraw[];
    f2 (*sA)[TP] = (f2(*)[TP])sraw;
    f2 (*sB)[TP] = (f2(*)[TP])(sraw + TILE_B);
    ldtile(sA, g_q + ((size_t)bh * Nn + ti * 64) * HDn, HDn, 1.f);
    ldtile(sB, g_w + ((size_t)bh * Nn + tj * 64) * HDn, HDn, 1.f);
    __syncthreads();
    EPI_COORDS;
    float acc[4][4] = {};
    wtile<true>(acc, sA, sB, wm, wn);
    float* out = g_LG + (size_t)bh * Nn * Nn + (size_t)(ti * 64) * Nn + tj * 64;
    const float* bet = g_beta + bh * Nn + tj * 64;
    bool dg = (ti == tj);
#pragma unroll
    for (int nf = 0; nf < 4; nf++) {
        int c = wn + nf * 8 + 2 * tig;
        int r0 = wm + g, r1 = r0 + 8;
        float v00 = acc[nf][0] * bet[c];
        float v01 = acc[nf][1] * bet[c + 1];
        float v10 = acc[nf][2] * bet[c];
        float v11 = acc[nf][3] * bet[c + 1];
        if (dg) {
            if (c     > r0) v00 = 0.f;
            if (c + 1 > r0) v01 = 0.f;
            if (c     > r1) v10 = 0.f;
            if (c + 1 > r1) v11 = 0.f;
        }
        out[r0 * Nn + c]     = v00;
        out[r0 * Nn + c + 1] = v01;
        out[r1 * Nn + c]     = v10;
        out[r1 * Nn + c + 1] = v11;
    }
}

// ---------------- logits: S = (qk^T - G C)*scale + Fc_t - Fc_j ----------------
__global__ void s_kernel() {
    int bx = blockIdx.x;
    int ti = bx >> 4, tj = bx & 15;
    if (tj > ti) return;
    int bh = blockIdx.y;
    extern __shared__ char sraw[];
    f2 (*sA)[TP] = (f2(*)[TP])sraw;
    f2 (*sB)[TP] = (f2(*)[TP])(sraw + TILE_B);
    EPI_COORDS;
    float acc[4][4] = {};
    ldtile(sA, g_q + ((size_t)bh * Nn + ti * 64) * HDn, HDn, 1.f);
    ldtile(sB, g_k + ((size_t)bh * Nn + tj * 64) * HDn, HDn, 1.f);
    __syncthreads();
    wtile<true>(acc, sA, sB, wm, wn);
    for (int sb = tj; sb <= ti; sb++) {
        __syncthreads();
        ldtile(sA, g_LG + (size_t)bh * Nn * Nn + (size_t)(ti * 64) * Nn + sb * 64, Nn, -1.f);
        ldtile(sB, g_C + (size_t)bh * Nn * Nn + (size_t)(sb * 64) * Nn + tj * 64, Nn, 1.f);
        __syncthreads();
        wtile<false>(acc, sA, sB, wm, wn);
    }
    const float* Fc = g_Fc + bh * Nn;
    float* out = g_S + (size_t)bh * Nn * Nn;
    bool dg = (ti == tj);
#pragma unroll
    for (int nf = 0; nf < 4; nf++) {
        int c = tj * 64 + wn + nf * 8 + 2 * tig;
        int r0 = ti * 64 + wm + g, r1 = r0 + 8;
        float f0 = Fc[r0], f1 = Fc[r1], fc0 = Fc[c], fc1 = Fc[c + 1];
        float v00 = acc[nf][0] * 0.125f + f0 - fc0;
        float v01 = acc[nf][1] * 0.125f + f0 - fc1;
        float v10 = acc[nf][2] * 0.125f + f1 - fc0;
        float v11 = acc[nf][3] * 0.125f + f1 - fc1;
        if (dg) {
            if (c     > r0) v00 = -1e30f;
            if (c + 1 > r0) v01 = -1e30f;
            if (c     > r1) v10 = -1e30f;
            if (c + 1 > r1) v11 = -1e30f;
        }
        out[(size_t)r0 * Nn + c]     = v00;
        out[(size_t)r0 * Nn + c + 1] = v01;
        out[(size_t)r1 * Nn + c]     = v10;
        out[(size_t)r1 * Nn + c + 1] = v11;
    }
}

// ---------------- row softmax (in place on g_S) ----------------
__global__ void softmax_kernel() {
    int t = blockIdx.x, bh = blockIdx.y, tid = threadIdx.x;
    float* row = g_S + (size_t)bh * Nn * Nn + (size_t)t * Nn;
    int Lr = ((t >> 6) + 1) << 6;
    __shared__ float red[4];
    float m = -3.4e38f;
    for (int idx = tid; idx < Lr; idx += 128) m = fmaxf(m, row[idx]);
#pragma unroll
    for (int o = 16; o; o >>= 1) m = fmaxf(m, __shfl_xor_sync(0xffffffffu, m, o));
    if ((tid & 31) == 0) red[tid >> 5] = m;
    __syncthreads();
    m = fmaxf(fmaxf(red[0], red[1]), fmaxf(red[2], red[3]));
    __syncthreads();
    float s = 0.f;
    for (int idx = tid; idx < Lr; idx += 128) {
        float e = expf(row[idx] - m);
        row[idx] = e;
        s += e;
    }
#pragma unroll
    for (int o = 16; o; o >>= 1) s += __shfl_xor_sync(0xffffffffu, s, o);
    if ((tid & 31) == 0) red[tid >> 5] = s;
    __syncthreads();
    s = red[0] + red[1] + red[2] + red[3];
    float inv = 1.f / s;
    for (int idx = tid; idx < Lr; idx += 128) row[idx] *= inv;
}

// ---------------- o = P @ v ----------------
__global__ void pv_kernel() {
    int ti = blockIdx.x, bh = blockIdx.y;
    extern __shared__ char sraw[];
    f2 (*sA)[TP] = (f2(*)[TP])sraw;
    f2 (*sB)[TP] = (f2(*)[TP])(sraw + TILE_B);
    EPI_COORDS;
    float acc[4][4] = {};
    for (int jb = 0; jb <= ti; jb++) {
        __syncthreads();
        ldtile(sA, g_S + (size_t)bh * Nn * Nn + (size_t)(ti * 64) * Nn + jb * 64, Nn, 1.f);
        ldtile(sB, g_v + ((size_t)bh * Nn + jb * 64) * HDn, HDn, 1.f);
        __syncthreads();
        wtile<false>(acc, sA, sB, wm, wn);
    }
    int b = bh >> 4, h = bh & 15;
#pragma unroll
    for (int nf = 0; nf < 4; nf++) {
        int c = h * 64 + wn + nf * 8 + 2 * tig;
        int r0 = b * Nn + ti * 64 + wm + g, r1 = r0 + 8;
        g_o[(size_t)r0 * Dn + c]     = acc[nf][0];
        g_o[(size_t)r0 * Dn + c + 1] = acc[nf][1];
        g_o[(size_t)r1 * Dn + c]     = acc[nf][2];
        g_o[(size_t)r1 * Dn + c + 1] = acc[nf][3];
    }
}

// ---------------- launch ----------------
extern "C" void kernel_launch(void* const* d_in, const int* in_sizes, int n_in,
                              void* d_out, int out_size) {
    const float* x   = (const float*)d_in[0];
    const float* Wq  = (const float*)d_in[1];
    const float* Wk  = (const float*)d_in[2];
    const float* Wv  = (const float*)d_in[3];
    const float* Wo  = (const float*)d_in[4];
    const float* Ww1 = (const float*)d_in[5];
    const float* Ww2 = (const float*)d_in[6];
    const float* Wb  = (const float*)d_in[7];
    const float* Wf  = (const float*)d_in[8];
    const float* dl  = (const float*)d_in[9];
    float* out = (float*)d_out;

    const int SM2 = 2 * (int)TILE_B;                         // 67584
    const int SMT = (int)TILE_B + 2 * 64 * 65 * (int)sizeof(float); // 67072

    static float *qf, *kf, *vf, *wf, *w1, *bb, *ff, *o_;
    static bool init = false;
    if (!init) {
        void* p;
        cudaGetSymbolAddress(&p, g_qf); qf = (float*)p;
        cudaGetSymbolAddress(&p, g_kf); kf = (float*)p;
        cudaGetSymbolAddress(&p, g_vf); vf = (float*)p;
        cudaGetSymbolAddress(&p, g_wf); wf = (float*)p;
        cudaGetSymbolAddress(&p, g_w1); w1 = (float*)p;
        cudaGetSymbolAddress(&p, g_bb); bb = (float*)p;
        cudaGetSymbolAddress(&p, g_ff); ff = (float*)p;
        cudaGetSymbolAddress(&p, g_o);  o_ = (float*)p;
        cudaFuncSetAttribute(gemm_tc,      cudaFuncAttributeMaxDynamicSharedMemorySize, SM2);
        cudaFuncSetAttribute(l_kernel,     cudaFuncAttributeMaxDynamicSharedMemorySize, SM2);
        cudaFuncSetAttribute(tinv_kernel,  cudaFuncAttributeMaxDynamicSharedMemorySize, SMT);
        cudaFuncSetAttribute(solve_kernel, cudaFuncAttributeMaxDynamicSharedMemorySize, SM2);
        cudaFuncSetAttribute(g_kernel,     cudaFuncAttributeMaxDynamicSharedMemorySize, SM2);
        cudaFuncSetAttribute(s_kernel,     cudaFuncAttributeMaxDynamicSharedMemorySize, SM2);
        cudaFuncSetAttribute(pv_kernel,    cudaFuncAttributeMaxDynamicSharedMemorySize, SM2);
        init = true;
    }

    dim3 thr(256);
    const int M = Bn * Nn;  // 2048

    // projections (tensor-core path; tiny N=16 ones stay scalar)
    gemm_tc<<<dim3(16, 32), thr, SM2>>>(x,  Wq,  qf, M, 1024, 1024);
    gemm_tc<<<dim3(16, 32), thr, SM2>>>(x,  Wk,  kf, M, 1024, 1024);
    gemm_tc<<<dim3(16, 32), thr, SM2>>>(x,  Wv,  vf, M, 1024, 1024);
    gemm_tc<<<dim3(1,  32), thr, SM2>>>(x,  Ww1, w1, M, 64,   1024);
    gemm_tc<<<dim3(16, 32), thr, SM2>>>(w1, Ww2, wf, M, 1024, 64);
    gemm_kernel<<<dim3(1, 32), thr>>>(x, Wb, bb, M, 16, 1024);
    gemm_kernel<<<dim3(1, 32), thr>>>(x, Wf, ff, M, 16, 1024);

    reorg_kernel<<<2048, thr>>>(dl);
    cumsum_kernel<<<32, thr>>>();

    l_kernel<<<dim3(256, 32), thr, SM2>>>();
    tinv_kernel<<<dim3(16, 32), thr, SMT>>>();

    for (int i = 0; i < NBn; i++)
        solve_kernel<<<dim3(i + 1, 32), thr, SM2>>>(i);

    g_kernel<<<dim3(256, 32), thr, SM2>>>();
    s_kernel<<<dim3(256, 32), thr, SM2>>>();
    softmax_kernel<<<dim3(1024, 32), dim3(128)>>>();
    pv_kernel<<<dim3(16, 32), thr, SM2>>>();

    gemm_tc<<<dim3(16, 32), thr, SM2>>>(o_, Wo, out, M, 1024, 1024);
}